// round 5
// baseline (speedup 1.0000x reference)
#include <cuda_runtime.h>
#include <cuda_bf16.h>

#define BB 64
#define NN 2048
#define DD 1024
#define SPLIT 32
#define ROWS_BLK (NN / SPLIT)   // 64 rows per item
#define ROWS_W 8                // rows per warp per item
#define SBUF 3                  // per-warp ring depth
#define NBLK 296                // persistent grid: 2 CTAs x 148 SMs
#define NITEMS (BB * SPLIT)     // 2048 work items
#define ESPLIT 8

// dyn smem: 8 warps * 3 slots * 4KB ring + 4KB reduce buffer
#define SMEM_K1 ((8 * SBUF * DD + DD) * 4)   // 102400 B

// Scratch (static device globals; no allocation)
__device__ float g_scores[BB * NN];
__device__ float g_part_m[NITEMS];
__device__ float g_part_l[NITEMS];
__device__ float g_part_mix[NITEMS * DD];        // 8 MB
__device__ float g_comb[BB * 2 * DD];            // [mix | output]
__device__ float g_out_part[BB * DD * ESPLIT];   // es-contiguous, 2 MB

__device__ __forceinline__ unsigned smem_u32(const void* p) {
    return (unsigned)__cvta_generic_to_shared(p);
}

// One 4KB row: lane i copies 16B chunks i, 32+i, ... (self-consistent:
// each lane later reads exactly the chunks it issued).
__device__ __forceinline__ void issue_row(float* dst, const float* src,
                                          int lane) {
#pragma unroll
    for (int c = 0; c < 8; c++) {
        const int f = (c * 32 + lane) * 4;
        unsigned sa = smem_u32(dst + f);
        asm volatile("cp.async.cg.shared.global [%0], [%1], 16;\n"
                     :: "r"(sa), "l"(src + f));
    }
}

// ---------------------------------------------------------------------------
// Kernel 1: persistent fused scores + online softmax + mix.
// 296 blocks, 256 threads. Block p handles items p, p+296, ... Each warp runs
// a flat cp.async stream over all its rows (8 per item); prefetch distance 2
// crosses item boundaries so DRAM never drains at epilogues.
// ---------------------------------------------------------------------------
__global__ __launch_bounds__(256, 2)
void k1_scores_mix(const float* __restrict__ output,
                   const float* __restrict__ context) {
    extern __shared__ float smem[];          // ring(24576) + buf(1024)
    __shared__ float sm[8], sl[8];

    const int p    = blockIdx.x;
    const int tid  = threadIdx.x;
    const int w    = tid >> 5;
    const int lane = tid & 31;

    float* ring = smem + w * (SBUF * DD);
    float* buf  = smem + 8 * SBUF * DD;      // 1024 floats, atomic reduce

    for (int i = tid; i < DD; i += 256) buf[i] = 0.f;
    __syncthreads();

    const int n_items = (NITEMS - p + NBLK - 1) / NBLK;  // 6 or 7
    const int F = n_items * ROWS_W;

    // flat row f -> global context row address for this warp
    auto src_of = [&](int f) -> const float* {
        const int it = f >> 3;
        const int t  = p + NBLK * it;        // item id == b*SPLIT+split
        const int b  = t >> 5, sp = t & 31;
        return context + ((size_t)b * NN + sp * ROWS_BLK + w * ROWS_W
                          + (f & 7)) * DD;
    };

    // Prologue
    issue_row(ring + 0 * DD, src_of(0), lane);
    asm volatile("cp.async.commit_group;\n");
    issue_row(ring + 1 * DD, src_of(1), lane);
    asm volatile("cp.async.commit_group;\n");

    float4 qv[8];
    float acc[32];
    float m = -1e30f, l = 0.f;

    for (int f = 0; f < F; f++) {
        const int it = f >> 3;
        const int t  = p + NBLK * it;
        const int b  = t >> 5, sp = t & 31;
        const int r  = f & 7;

        if (r == 0) {                        // new item: load q, reset state
            const float* q = output + (size_t)b * DD;
#pragma unroll
            for (int j = 0; j < 8; j++)
                qv[j] = *(const float4*)(q + j * 128 + lane * 4);
#pragma unroll
            for (int k = 0; k < 32; k++) acc[k] = 0.f;
            m = -1e30f; l = 0.f;
        }

        asm volatile("cp.async.wait_group 1;\n");
        if (f + 2 < F)
            issue_row(ring + ((f + 2) % SBUF) * DD, src_of(f + 2), lane);
        asm volatile("cp.async.commit_group;\n");

        const float* row = ring + (f % SBUF) * DD;
        float4 cv[8];
#pragma unroll
        for (int j = 0; j < 8; j++)
            cv[j] = *(const float4*)(row + j * 128 + lane * 4);

        float s0 = 0.f, s1 = 0.f, s2 = 0.f, s3 = 0.f;
#pragma unroll
        for (int j = 0; j < 8; j++) {
            s0 = fmaf(qv[j].x, cv[j].x, s0);
            s1 = fmaf(qv[j].y, cv[j].y, s1);
            s2 = fmaf(qv[j].z, cv[j].z, s2);
            s3 = fmaf(qv[j].w, cv[j].w, s3);
        }
        float s = (s0 + s1) + (s2 + s3);
#pragma unroll
        for (int off = 16; off; off >>= 1)
            s += __shfl_xor_sync(0xffffffffu, s, off);

        if (lane == 0)
            g_scores[(size_t)b * NN + sp * ROWS_BLK + w * ROWS_W + r] = s;

        if (s <= m) {                        // warp-uniform branch
            const float pp = __expf(s - m);
            l += pp;
#pragma unroll
            for (int j = 0; j < 8; j++) {
                acc[4 * j + 0] = fmaf(pp, cv[j].x, acc[4 * j + 0]);
                acc[4 * j + 1] = fmaf(pp, cv[j].y, acc[4 * j + 1]);
                acc[4 * j + 2] = fmaf(pp, cv[j].z, acc[4 * j + 2]);
                acc[4 * j + 3] = fmaf(pp, cv[j].w, acc[4 * j + 3]);
            }
        } else {
            const float c = __expf(m - s);
            l = fmaf(l, c, 1.f);
#pragma unroll
            for (int j = 0; j < 8; j++) {
                acc[4 * j + 0] = fmaf(acc[4 * j + 0], c, cv[j].x);
                acc[4 * j + 1] = fmaf(acc[4 * j + 1], c, cv[j].y);
                acc[4 * j + 2] = fmaf(acc[4 * j + 2], c, cv[j].z);
                acc[4 * j + 3] = fmaf(acc[4 * j + 3], c, cv[j].w);
            }
            m = s;
        }

        if (r == 7) {                        // item epilogue
            if (lane == 0) { sm[w] = m; sl[w] = l; }
            __syncthreads();

            float M = sm[0];
#pragma unroll
            for (int s2 = 1; s2 < 8; s2++) M = fmaxf(M, sm[s2]);
            float L = 0.f;
#pragma unroll
            for (int s2 = 0; s2 < 8; s2++) L += sl[s2] * __expf(sm[s2] - M);

            const float scale = __expf(m - M);
#pragma unroll
            for (int j = 0; j < 8; j++) {
                const int d = j * 128 + lane * 4;
                atomicAdd(&buf[d + 0], acc[4 * j + 0] * scale);
                atomicAdd(&buf[d + 1], acc[4 * j + 1] * scale);
                atomicAdd(&buf[d + 2], acc[4 * j + 2] * scale);
                atomicAdd(&buf[d + 3], acc[4 * j + 3] * scale);
            }
            __syncthreads();

            for (int i = tid; i < DD; i += 256) {
                g_part_mix[(size_t)t * DD + i] = buf[i];
                buf[i] = 0.f;                // rezero for next item
            }
            if (tid == 0) { g_part_m[t] = M; g_part_l[t] = L; }
            // next item's atomics are gated by its own first __syncthreads
        }
    }
}

// ---------------------------------------------------------------------------
// Kernel 2: combine splits. grid (BB, 2): y=0 mix+comb, y=1 attn+copy.
// ---------------------------------------------------------------------------
__global__ __launch_bounds__(256)
void k2_combine(const float* __restrict__ output,
                float* __restrict__ attn_out) {
    const int b   = blockIdx.x;
    const int tid = threadIdx.x;

    float M = -1e30f;
#pragma unroll
    for (int s = 0; s < SPLIT; s++) M = fmaxf(M, g_part_m[b * SPLIT + s]);
    float L = 0.f;
#pragma unroll
    for (int s = 0; s < SPLIT; s++)
        L += g_part_l[b * SPLIT + s] * __expf(g_part_m[b * SPLIT + s] - M);
    const float invL = 1.f / L;

    if (blockIdx.y == 0) {
        // mix: thread owns 4 consecutive d, 32 unrolled float4 loads
        const int d0 = tid * 4;
        float4 r = make_float4(0.f, 0.f, 0.f, 0.f);
#pragma unroll
        for (int s = 0; s < SPLIT; s++) {
            const float wg = __expf(g_part_m[b * SPLIT + s] - M);
            float4 v = *(const float4*)
                (&g_part_mix[(size_t)(b * SPLIT + s) * DD + d0]);
            r.x = fmaf(v.x, wg, r.x);
            r.y = fmaf(v.y, wg, r.y);
            r.z = fmaf(v.z, wg, r.z);
            r.w = fmaf(v.w, wg, r.w);
        }
        r.x *= invL; r.y *= invL; r.z *= invL; r.w *= invL;
        *(float4*)(&g_comb[(size_t)b * 2 * DD + d0]) = r;
    } else {
        // attn + copy output into comb
#pragma unroll
        for (int i = 0; i < 8; i++) {
            const int n = tid + i * 256;
            attn_out[(size_t)b * NN + n] =
                __expf(g_scores[(size_t)b * NN + n] - M) * invL;
        }
        const int d0 = tid * 4;
        *(float4*)(&g_comb[(size_t)b * 2 * DD + DD + d0]) =
            *(const float4*)(output + (size_t)b * DD + d0);
    }
}

// ---------------------------------------------------------------------------
// Kernel 3: out_part = comb @ W^T. 64d x 64b x 256e per block,
// grid (16, ESPLIT=8) = 128 blocks, 256 threads, 4x4 reg tile.
// d-major smem, pad 33: stores bank (r+c)%32 conflict-free, scalar reads
// Ws[dg+16j][k] bank (dg+16j+k)%32 conflict-free (proven R3 pattern).
// ---------------------------------------------------------------------------
__global__ __launch_bounds__(256)
void k3_gemm(const float* __restrict__ W) {
    const int dt  = blockIdx.x;
    const int es  = blockIdx.y;
    const int tid = threadIdx.x;
    const int d0  = dt * 64;
    const int e0  = es * 256;
    const int dg  = tid & 15;
    const int bg  = tid >> 4;

    __shared__ float Ws[64][33];  // [d][k]
    __shared__ float Cs[64][33];  // [b][k]

    float acc[4][4];
#pragma unroll
    for (int i = 0; i < 4; i++)
#pragma unroll
        for (int j = 0; j < 4; j++) acc[i][j] = 0.f;

    for (int ec = 0; ec < 256; ec += 32) {
#pragma unroll
        for (int i = 0; i < 8; i++) {
            int idx = tid + i * 256;
            int r = idx >> 5, c = idx & 31;   // r: d/b row, c: k
            Ws[r][c] = W[(size_t)(d0 + r) * (2 * DD) + e0 + ec + c];
            Cs[r][c] = g_comb[(size_t)r * (2 * DD) + e0 + ec + c];
        }
        __syncthreads();
#pragma unroll
        for (int k = 0; k < 32; k++) {
            float wv[4], cvv[4];
#pragma unroll
            for (int j = 0; j < 4; j++) wv[j] = Ws[dg + 16 * j][k];
#pragma unroll
            for (int i = 0; i < 4; i++) cvv[i] = Cs[bg + 16 * i][k];
#pragma unroll
            for (int i = 0; i < 4; i++)
#pragma unroll
                for (int j = 0; j < 4; j++)
                    acc[i][j] = fmaf(cvv[i], wv[j], acc[i][j]);
        }
        __syncthreads();
    }

#pragma unroll
    for (int i = 0; i < 4; i++)
#pragma unroll
        for (int j = 0; j < 4; j++) {
            const int bidx = bg + 16 * i;
            const int didx = d0 + dg + 16 * j;
            g_out_part[((size_t)bidx * DD + didx) * ESPLIT + es] = acc[i][j];
        }
}

// ---------------------------------------------------------------------------
// Kernel 4: es-contiguous partial reduce + bias + tanh.
// ---------------------------------------------------------------------------
__global__ void k4_final(const float* __restrict__ bias,
                         float* __restrict__ out) {
    const int idx = blockIdx.x * blockDim.x + threadIdx.x;  // 0..65535
    const int d = idx & (DD - 1);
    const float4 a = *(const float4*)(&g_out_part[(size_t)idx * ESPLIT]);
    const float4 b4 = *(const float4*)(&g_out_part[(size_t)idx * ESPLIT + 4]);
    float a0 = (a.x + a.y) + (a.z + a.w);
    float a1 = (b4.x + b4.y) + (b4.z + b4.w);
    float v = a0 + a1 + bias[d];
    float r;
    asm("tanh.approx.f32 %0, %1;" : "=f"(r) : "f"(v));
    out[idx] = r;
}

// ---------------------------------------------------------------------------
extern "C" void kernel_launch(void* const* d_in, const int* in_sizes, int n_in,
                              void* d_out, int out_size) {
    const float* output  = (const float*)d_in[0];  // (64,1,1024)
    const float* context = (const float*)d_in[1];  // (64,2048,1024)
    const float* W_out   = (const float*)d_in[2];  // (1024,2048)
    const float* b_out   = (const float*)d_in[3];  // (1024)

    float* out  = (float*)d_out;       // (64,1,1024) first
    float* attn = out + BB * DD;       // (64,1,2048) second

    static int smem_set = 0;
    if (!smem_set) {
        cudaFuncSetAttribute(k1_scores_mix,
                             cudaFuncAttributeMaxDynamicSharedMemorySize,
                             SMEM_K1);
        smem_set = 1;
    }

    k1_scores_mix<<<NBLK, 256, SMEM_K1>>>(output, context);
    k2_combine<<<dim3(BB, 2), 256>>>(output, attn);
    k3_gemm<<<dim3(16, ESPLIT), 256>>>(W_out);
    k4_final<<<256, 256>>>(b_out, out);
}

// round 6
// speedup vs baseline: 1.0871x; 1.0871x over previous
#include <cuda_runtime.h>
#include <cuda_bf16.h>

#define BB 64
#define NN 2048
#define DD 1024
#define SPLIT 32
#define ROWS_BLK (NN / SPLIT)   // 64 rows per block
#define ROWS_W 8                // rows per warp
#define SBUF 3                  // per-warp ring depth
#define ESPLIT 8

#define SMEM_K1 (8 * SBUF * DD * 4)   // 8 warps * 3 slots * 4KB = 98304 B

// Scratch (static device globals; no allocation)
__device__ float g_scores[BB * NN];
__device__ float g_part_m[BB * SPLIT];
__device__ float g_part_l[BB * SPLIT];
__device__ float g_part_mix[BB * SPLIT * DD];    // 8 MB
__device__ float g_comb[BB * 2 * DD];            // [mix | output]
__device__ float g_out_part[BB * DD * ESPLIT];   // es-contiguous, 2 MB

__device__ __forceinline__ unsigned smem_u32(const void* p) {
    return (unsigned)__cvta_generic_to_shared(p);
}

// One 4KB row: lane i copies 16B chunks i, 32+i, ... (self-consistent:
// each lane later reads exactly the chunks it issued).
__device__ __forceinline__ void issue_row(float* dst, const float* src,
                                          int lane) {
#pragma unroll
    for (int c = 0; c < 8; c++) {
        const int f = (c * 32 + lane) * 4;   // float index
        unsigned sa = smem_u32(dst + f);
        asm volatile("cp.async.cg.shared.global [%0], [%1], 16;\n"
                     :: "r"(sa), "l"(src + f));
    }
}

// ---------------------------------------------------------------------------
// Kernel 1: barrier-free per-warp cp.async pipelines (R3-proven).
// grid (SPLIT, BB), 256 threads. Warp w owns rows [w*8, w*8+8) and a private
// 3-slot smem ring, fully unrolled -> compile-time ring indices.
// ---------------------------------------------------------------------------
__global__ __launch_bounds__(256, 2)
void k1_scores_mix(const float* __restrict__ output,
                   const float* __restrict__ context) {
    extern __shared__ float smem[];          // 8 * SBUF * DD floats
    __shared__ float sm[8], sl[8];

    const int split = blockIdx.x;
    const int b     = blockIdx.y;
    const int tid   = threadIdx.x;
    const int w     = tid >> 5;
    const int lane  = tid & 31;

    const float* q   = output + (size_t)b * DD;
    const float* ctx = context + (size_t)b * NN * DD
                               + (size_t)(split * ROWS_BLK + w * ROWS_W) * DD;
    float* ring = smem + w * (SBUF * DD);

    float4 qv[8];
#pragma unroll
    for (int j = 0; j < 8; j++)
        qv[j] = *(const float4*)(q + j * 128 + lane * 4);

    float acc[32];
#pragma unroll
    for (int k = 0; k < 32; k++) acc[k] = 0.f;
    float m = -1e30f, l = 0.f;

    // Prologue: rows 0,1 in flight
#pragma unroll
    for (int ps = 0; ps < SBUF - 1; ps++) {
        issue_row(ring + ps * DD, ctx + (size_t)ps * DD, lane);
        asm volatile("cp.async.commit_group;\n");
    }

#pragma unroll
    for (int r = 0; r < ROWS_W; r++) {
        asm volatile("cp.async.wait_group 1;\n");
        __syncwarp();

        if (r + SBUF - 1 < ROWS_W)
            issue_row(ring + ((r + SBUF - 1) % SBUF) * DD,
                      ctx + (size_t)(r + SBUF - 1) * DD, lane);
        asm volatile("cp.async.commit_group;\n");

        const float* row = ring + (r % SBUF) * DD;
        float4 cv[8];
#pragma unroll
        for (int j = 0; j < 8; j++)
            cv[j] = *(const float4*)(row + j * 128 + lane * 4);

        float s0 = 0.f, s1 = 0.f, s2 = 0.f, s3 = 0.f;
#pragma unroll
        for (int j = 0; j < 8; j++) {
            s0 = fmaf(qv[j].x, cv[j].x, s0);
            s1 = fmaf(qv[j].y, cv[j].y, s1);
            s2 = fmaf(qv[j].z, cv[j].z, s2);
            s3 = fmaf(qv[j].w, cv[j].w, s3);
        }
        float s = (s0 + s1) + (s2 + s3);
#pragma unroll
        for (int off = 16; off; off >>= 1)
            s += __shfl_xor_sync(0xffffffffu, s, off);

        if (lane == 0)
            g_scores[(size_t)b * NN + split * ROWS_BLK + w * ROWS_W + r] = s;

        // Branchy online softmax (s warp-uniform -> no divergence)
        if (s <= m) {
            const float p = __expf(s - m);
            l += p;
#pragma unroll
            for (int j = 0; j < 8; j++) {
                acc[4 * j + 0] = fmaf(p, cv[j].x, acc[4 * j + 0]);
                acc[4 * j + 1] = fmaf(p, cv[j].y, acc[4 * j + 1]);
                acc[4 * j + 2] = fmaf(p, cv[j].z, acc[4 * j + 2]);
                acc[4 * j + 3] = fmaf(p, cv[j].w, acc[4 * j + 3]);
            }
        } else {
            const float c = __expf(m - s);
            l = fmaf(l, c, 1.f);
#pragma unroll
            for (int j = 0; j < 8; j++) {
                acc[4 * j + 0] = fmaf(acc[4 * j + 0], c, cv[j].x);
                acc[4 * j + 1] = fmaf(acc[4 * j + 1], c, cv[j].y);
                acc[4 * j + 2] = fmaf(acc[4 * j + 2], c, cv[j].z);
                acc[4 * j + 3] = fmaf(acc[4 * j + 3], c, cv[j].w);
            }
            m = s;
        }
    }

    // Drain all async groups, then block combine (one barrier).
    asm volatile("cp.async.wait_group 0;\n");
    if (lane == 0) { sm[w] = m; sl[w] = l; }
    __syncthreads();

    float M = sm[0];
#pragma unroll
    for (int s2 = 1; s2 < 8; s2++) M = fmaxf(M, sm[s2]);
    float L = 0.f;
#pragma unroll
    for (int s2 = 0; s2 < 8; s2++) L += sl[s2] * __expf(sm[s2] - M);

    const float scale = __expf(m - M);
    float* red = smem;                       // reuse ring region: 8 * DD
#pragma unroll
    for (int j = 0; j < 8; j++) {
        float4 v = make_float4(acc[4 * j + 0] * scale, acc[4 * j + 1] * scale,
                               acc[4 * j + 2] * scale, acc[4 * j + 3] * scale);
        *(float4*)(red + w * DD + j * 128 + lane * 4) = v;
    }
    __syncthreads();

    {
        const int d0 = tid * 4;
        float4 r = *(const float4*)(red + d0);
#pragma unroll
        for (int ww = 1; ww < 8; ww++) {
            float4 v = *(const float4*)(red + ww * DD + d0);
            r.x += v.x; r.y += v.y; r.z += v.z; r.w += v.w;
        }
        const int ps = b * SPLIT + split;
        *(float4*)(&g_part_mix[(size_t)ps * DD + d0]) = r;
        if (tid == 0) { g_part_m[ps] = M; g_part_l[ps] = L; }
    }
}

// ---------------------------------------------------------------------------
// Kernel 2: combine splits. grid (BB, 2): y=0 mix+comb, y=1 attn+copy.
// ---------------------------------------------------------------------------
__global__ __launch_bounds__(256)
void k2_combine(const float* __restrict__ output,
                float* __restrict__ attn_out) {
    const int b   = blockIdx.x;
    const int tid = threadIdx.x;

    float M = -1e30f;
#pragma unroll
    for (int s = 0; s < SPLIT; s++) M = fmaxf(M, g_part_m[b * SPLIT + s]);
    float L = 0.f;
#pragma unroll
    for (int s = 0; s < SPLIT; s++)
        L += g_part_l[b * SPLIT + s] * __expf(g_part_m[b * SPLIT + s] - M);
    const float invL = 1.f / L;

    if (blockIdx.y == 0) {
        const int d0 = tid * 4;
        float4 r = make_float4(0.f, 0.f, 0.f, 0.f);
#pragma unroll
        for (int s = 0; s < SPLIT; s++) {
            const float wg = __expf(g_part_m[b * SPLIT + s] - M);
            float4 v = *(const float4*)
                (&g_part_mix[(size_t)(b * SPLIT + s) * DD + d0]);
            r.x = fmaf(v.x, wg, r.x);
            r.y = fmaf(v.y, wg, r.y);
            r.z = fmaf(v.z, wg, r.z);
            r.w = fmaf(v.w, wg, r.w);
        }
        r.x *= invL; r.y *= invL; r.z *= invL; r.w *= invL;
        *(float4*)(&g_comb[(size_t)b * 2 * DD + d0]) = r;
    } else {
#pragma unroll
        for (int i = 0; i < 8; i++) {
            const int n = tid + i * 256;
            attn_out[(size_t)b * NN + n] =
                __expf(g_scores[(size_t)b * NN + n] - M) * invL;
        }
        const int d0 = tid * 4;
        *(float4*)(&g_comb[(size_t)b * 2 * DD + DD + d0]) =
            *(const float4*)(output + (size_t)b * DD + d0);
    }
}

// ---------------------------------------------------------------------------
// Kernel 3: out_part = comb @ W^T. 64d x 64b x 256e per block,
// grid (16, ESPLIT=8) = 128 blocks, 256 threads, 4x4 reg tile.
// d-major smem, pad 33 -> conflict-free stores and broadcast reads.
// ---------------------------------------------------------------------------
__global__ __launch_bounds__(256)
void k3_gemm(const float* __restrict__ W) {
    const int dt  = blockIdx.x;
    const int es  = blockIdx.y;
    const int tid = threadIdx.x;
    const int d0  = dt * 64;
    const int e0  = es * 256;
    const int dg  = tid & 15;
    const int bg  = tid >> 4;

    __shared__ float Ws[64][33];  // [d][k]
    __shared__ float Cs[64][33];  // [b][k]

    float acc[4][4];
#pragma unroll
    for (int i = 0; i < 4; i++)
#pragma unroll
        for (int j = 0; j < 4; j++) acc[i][j] = 0.f;

    for (int ec = 0; ec < 256; ec += 32) {
#pragma unroll
        for (int i = 0; i < 8; i++) {
            int idx = tid + i * 256;
            int r = idx >> 5, c = idx & 31;
            Ws[r][c] = W[(size_t)(d0 + r) * (2 * DD) + e0 + ec + c];
            Cs[r][c] = g_comb[(size_t)r * (2 * DD) + e0 + ec + c];
        }
        __syncthreads();
#pragma unroll
        for (int k = 0; k < 32; k++) {
            float wv[4], cvv[4];
#pragma unroll
            for (int j = 0; j < 4; j++) wv[j] = Ws[dg + 16 * j][k];
#pragma unroll
            for (int i = 0; i < 4; i++) cvv[i] = Cs[bg + 16 * i][k];
#pragma unroll
            for (int i = 0; i < 4; i++)
#pragma unroll
                for (int j = 0; j < 4; j++)
                    acc[i][j] = fmaf(cvv[i], wv[j], acc[i][j]);
        }
        __syncthreads();
    }

#pragma unroll
    for (int i = 0; i < 4; i++)
#pragma unroll
        for (int j = 0; j < 4; j++) {
            const int bidx = bg + 16 * i;
            const int didx = d0 + dg + 16 * j;
            g_out_part[((size_t)bidx * DD + didx) * ESPLIT + es] = acc[i][j];
        }
}

// ---------------------------------------------------------------------------
// Kernel 4: es-contiguous partial reduce + bias + tanh.
// ---------------------------------------------------------------------------
__global__ void k4_final(const float* __restrict__ bias,
                         float* __restrict__ out) {
    const int idx = blockIdx.x * blockDim.x + threadIdx.x;  // 0..65535
    const int d = idx & (DD - 1);
    const float4 a = *(const float4*)(&g_out_part[(size_t)idx * ESPLIT]);
    const float4 b4 = *(const float4*)(&g_out_part[(size_t)idx * ESPLIT + 4]);
    float a0 = (a.x + a.y) + (a.z + a.w);
    float a1 = (b4.x + b4.y) + (b4.z + b4.w);
    float v = a0 + a1 + bias[d];
    float r;
    asm("tanh.approx.f32 %0, %1;" : "=f"(r) : "f"(v));
    out[idx] = r;
}

// ---------------------------------------------------------------------------
extern "C" void kernel_launch(void* const* d_in, const int* in_sizes, int n_in,
                              void* d_out, int out_size) {
    const float* output  = (const float*)d_in[0];  // (64,1,1024)
    const float* context = (const float*)d_in[1];  // (64,2048,1024)
    const float* W_out   = (const float*)d_in[2];  // (1024,2048)
    const float* b_out   = (const float*)d_in[3];  // (1024)

    float* out  = (float*)d_out;       // (64,1,1024) first
    float* attn = out + BB * DD;       // (64,1,2048) second

    static int smem_set = 0;
    if (!smem_set) {
        cudaFuncSetAttribute(k1_scores_mix,
                             cudaFuncAttributeMaxDynamicSharedMemorySize,
                             SMEM_K1);
        smem_set = 1;
    }

    k1_scores_mix<<<dim3(SPLIT, BB), 256, SMEM_K1>>>(output, context);
    k2_combine<<<dim3(BB, 2), 256>>>(output, attn);
    k3_gemm<<<dim3(16, ESPLIT), 256>>>(W_out);
    k4_final<<<256, 256>>>(b_out, out);
}